// round 7
// baseline (speedup 1.0000x reference)
#include <cuda_runtime.h>
#include <cstdint>

typedef unsigned long long ull;
#define DEV_INLINE __device__ __forceinline__

// ---------------- problem constants ----------------
constexpr int Bb = 8, Nn = 1024, Cc = 768, Hh = 12, Dd = 64, Mm = 128;
constexpr int BN3C = Bb * Nn * 3 * Cc;          // qkv scratch
constexpr int BHNM = Bb * Hh * Nn * Mm;         // feature maps
constexpr int BNC  = Bb * Nn * Cc;              // attention output

constexpr int SLAB = 16 * 132;                  // one k-slab (transposed, padded)

// ---------------- scratch (no allocation allowed) ----------------
__device__ float g_qkv[BN3C];   // [b][n][t*C + h*D + d], t in {q,k,v}
__device__ float g_qf[BHNM];    // [b][h][n][m]
__device__ float g_kf[BHNM];    // [b][h][n][m]
__device__ float g_att[BNC];    // [b][n][h*D + d]  (== [8192][768])

// ---------------- f32x2 helpers (sm_100+) ----------------
DEV_INLINE ull pack2(float lo, float hi) {
    ull r;
    asm("mov.b64 %0, {%1, %2};" : "=l"(r) : "f"(lo), "f"(hi));
    return r;
}
DEV_INLINE float2 unpack2(ull v) {
    float2 f;
    asm("mov.b64 {%0, %1}, %2;" : "=f"(f.x), "=f"(f.y) : "l"(v));
    return f;
}
DEV_INLINE void fma2(ull& d, ull a, ull b) {
    asm("fma.rn.f32x2 %0, %1, %2, %0;" : "+l"(d) : "l"(a), "l"(b));
}

// swizzle key for S staging: bits {0,1,2,4} <- (j>>3) bits {0,1,2,3}
// keeps bit 3 free so i's ty-bit never collides -> conflict-free stores.
DEV_INLINE int swiz(int j) {
    int g = j >> 3;
    return (g & 7) | ((g & 8) << 1);
}

// store one 16x128 transposed slab pair into As/Bs (shared helper pattern)
#define STORE_SLAB(Sm, v0, v1, cb, r)                                          \
    do {                                                                       \
        Sm[(cb + 0) * 132 + r]      = v0.x; Sm[(cb + 1) * 132 + r]      = v0.y;\
        Sm[(cb + 2) * 132 + r]      = v0.z; Sm[(cb + 3) * 132 + r]      = v0.w;\
        Sm[(cb + 0) * 132 + 64 + r] = v1.x; Sm[(cb + 1) * 132 + 64 + r] = v1.y;\
        Sm[(cb + 2) * 132 + 64 + r] = v1.z; Sm[(cb + 3) * 132 + 64 + r] = v1.w;\
    } while (0)

// inner 16-step f32x2 microkernel over one slab pair
#define MICRO_FMA(ACC, Asb, Bsb, ty, tx)                                       \
    _Pragma("unroll")                                                          \
    for (int kk = 0; kk < 16; ++kk) {                                          \
        const ull* ap = (const ull*)(Asb + kk * 132 + ty * 8);                 \
        ull a0 = ap[0], a1 = ap[1], a2 = ap[2], a3 = ap[3];                    \
        const float4* bp = (const float4*)(Bsb + kk * 132 + tx * 8);           \
        float4 bq0 = bp[0], bq1 = bp[1];                                       \
        ull bd[8];                                                             \
        bd[0] = pack2(bq0.x, bq0.x); bd[1] = pack2(bq0.y, bq0.y);              \
        bd[2] = pack2(bq0.z, bq0.z); bd[3] = pack2(bq0.w, bq0.w);              \
        bd[4] = pack2(bq1.x, bq1.x); bd[5] = pack2(bq1.y, bq1.y);              \
        bd[6] = pack2(bq1.z, bq1.z); bd[7] = pack2(bq1.w, bq1.w);              \
        _Pragma("unroll")                                                      \
        for (int jj = 0; jj < 8; ++jj) {                                       \
            fma2(ACC[0][jj], a0, bd[jj]);                                      \
            fma2(ACC[1][jj], a1, bd[jj]);                                      \
            fma2(ACC[2][jj], a2, bd[jj]);                                      \
            fma2(ACC[3][jj], a3, bd[jj]);                                      \
        }                                                                      \
    }

// =====================================================================
// Generic NT GEMM: C[m,n] = sum_k A[m*K+k] * B[n*K+k] (+ bias[n])
// BM=BN=128, BK=16, 256 threads, 8x8 micro-tile (rows packed in f32x2).
// Double-buffered slabs: ONE barrier per k-chunk. Register prefetch
// hides LDG latency under the FMA loop.
// =====================================================================
__global__ __launch_bounds__(256)
void gemm_nt_kernel(const float* __restrict__ A, const float* __restrict__ Bw,
                    const float* __restrict__ bias, float* __restrict__ C,
                    int M, int N, int K)
{
    __shared__ float As[2 * SLAB];
    __shared__ float Bs[2 * SLAB];

    const int tid = threadIdx.x;
    const int ty = tid >> 4, tx = tid & 15;
    const int m0 = blockIdx.y << 7, n0 = blockIdx.x << 7;

    ull acc[4][8];
#pragma unroll
    for (int i = 0; i < 4; ++i)
#pragma unroll
        for (int j = 0; j < 8; ++j) acc[i][j] = 0ull;

    const int r  = tid >> 2;     // 0..63
    const int c4 = tid & 3;      // which float4 along k
    const int cb = c4 * 4;
    const float* Ap  = A  + (size_t)(m0 + r)      * K + c4 * 4;
    const float* Ap2 = A  + (size_t)(m0 + 64 + r) * K + c4 * 4;
    const float* Bp  = Bw + (size_t)(n0 + r)      * K + c4 * 4;
    const float* Bp2 = Bw + (size_t)(n0 + 64 + r) * K + c4 * 4;

    // prefetch first slab
    float4 pa0 = *(const float4*)(Ap);
    float4 pa1 = *(const float4*)(Ap2);
    float4 pb0 = *(const float4*)(Bp);
    float4 pb1 = *(const float4*)(Bp2);

#pragma unroll 1
    for (int k0 = 0; k0 < K; k0 += 16) {
        const int p = (k0 >> 4) & 1;
        float* Asb = As + p * SLAB;
        float* Bsb = Bs + p * SLAB;
        STORE_SLAB(Asb, pa0, pa1, cb, r);
        STORE_SLAB(Bsb, pb0, pb1, cb, r);
        __syncthreads();                 // slab p visible; readers of p done 2 iters ago
        if (k0 + 16 < K) {               // prefetch next slab (retires under FMAs)
            pa0 = *(const float4*)(Ap  + k0 + 16);
            pa1 = *(const float4*)(Ap2 + k0 + 16);
            pb0 = *(const float4*)(Bp  + k0 + 16);
            pb1 = *(const float4*)(Bp2 + k0 + 16);
        }
        MICRO_FMA(acc, Asb, Bsb, ty, tx);
    }

    // epilogue
#pragma unroll
    for (int ip = 0; ip < 4; ++ip) {
        float lo[8], hi[8];
#pragma unroll
        for (int jj = 0; jj < 8; ++jj) {
            float2 t = unpack2(acc[ip][jj]);
            lo[jj] = t.x; hi[jj] = t.y;
        }
        if (bias) {
#pragma unroll
            for (int jj = 0; jj < 8; ++jj) {
                float bv = bias[n0 + tx * 8 + jj];
                lo[jj] += bv; hi[jj] += bv;
            }
        }
        size_t rowL = (size_t)(m0 + ty * 8 + ip * 2) * N + n0 + tx * 8;
        *(float4*)(C + rowL)     = make_float4(lo[0], lo[1], lo[2], lo[3]);
        *(float4*)(C + rowL + 4) = make_float4(lo[4], lo[5], lo[6], lo[7]);
        size_t rowH = rowL + N;
        *(float4*)(C + rowH)     = make_float4(hi[0], hi[1], hi[2], hi[3]);
        *(float4*)(C + rowH + 4) = make_float4(hi[4], hi[5], hi[6], hi[7]);
    }
}

// =====================================================================
// Feature map: qf/kf[b,h,n,m] = exp( (z @ rand_h)[m] - 0.5*|z|^2 ) * M^-0.5
// with z = (q or k)[b,h,n,:] * SCALE^0.5.
// grid: (N/16, H, 2*B) [z&1 -> q/k], block: 128 threads (thread = one m).
// =====================================================================
__global__ __launch_bounds__(128)
void feat_kernel(const float* __restrict__ qkv, const float* __restrict__ rand_m,
                 float* __restrict__ qf, float* __restrict__ kf)
{
    __shared__ float R[64 * 128];   // [d][m] for this head (32 KB)
    __shared__ float Z[16 * 64];    // 16 scaled rows
    __shared__ float SQ[16];

    const int tid = threadIdx.x;
    const int n0 = blockIdx.x * 16;
    const int h  = blockIdx.y;
    const int b  = blockIdx.z >> 1;
    const int which = blockIdx.z & 1;   // 0 = q, 1 = k

    // load rand head tile (same layout, straight copy)
#pragma unroll
    for (int p = 0; p < 16; ++p) {
        int f4 = tid + p * 128;
        *(float4*)(R + f4 * 4) = *(const float4*)(rand_m + (size_t)h * 8192 + f4 * 4);
    }
    // load & scale z rows
    const float sqc = 0.3535533905932738f;   // SCALE^0.5 = 64^-0.25
#pragma unroll
    for (int p = 0; p < 2; ++p) {
        int f4 = tid + p * 128;
        int rr = f4 >> 4, dq = f4 & 15;
        float4 z = *(const float4*)(qkv + (size_t)(b * Nn + n0 + rr) * (3 * Cc)
                                    + which * Cc + h * Dd + dq * 4);
        z.x *= sqc; z.y *= sqc; z.z *= sqc; z.w *= sqc;
        *(float4*)(Z + rr * 64 + dq * 4) = z;
    }
    __syncthreads();
    if (tid < 16) {
        float s = 0.f;
#pragma unroll
        for (int d = 0; d < 64; ++d) { float zz = Z[tid * 64 + d]; s += zz * zz; }
        SQ[tid] = 0.5f * s;
    }
    __syncthreads();

    // this thread's column of rand: keep in registers
    float Rreg[64];
#pragma unroll
    for (int d = 0; d < 64; ++d) Rreg[d] = R[d * 128 + tid];

    float* outp = (which ? kf : qf)
                + ((size_t)(b * Hh + h) * Nn + n0) * Mm + tid;
    const float invSqrtM = 0.08838834764831845f;   // 128^-0.5
#pragma unroll 1
    for (int rr = 0; rr < 16; ++rr) {
        float acc = 0.f;
#pragma unroll
        for (int dq = 0; dq < 16; ++dq) {
            float4 z = *(const float4*)(Z + rr * 64 + dq * 4);
            acc = fmaf(z.x, Rreg[dq * 4 + 0], acc);
            acc = fmaf(z.y, Rreg[dq * 4 + 1], acc);
            acc = fmaf(z.z, Rreg[dq * 4 + 2], acc);
            acc = fmaf(z.w, Rreg[dq * 4 + 3], acc);
        }
        outp[(size_t)rr * Mm] = expf(acc - SQ[rr]) * invSqrtM;
    }
}

// =====================================================================
// Fused linear attention per (b,h, 128-row q tile):
//   out[i,:] = ( sum_j S[i,j]*v[j,:] ) / max( sum_j |S[i,j]|, 1e-12 )
//   with S = qf_tile @ kf^T, never materialized in HBM.
// 256 threads. Dynamic smem ~129.5 KB. Double-buffered slabs + reg prefetch.
// =====================================================================
constexpr int ATT_SMEM_FLOATS = 2 * SLAB * 2 + 128 * 128 + 128 * 64 + 128;
constexpr int ATT_SMEM_BYTES  = ATT_SMEM_FLOATS * 4;

__global__ __launch_bounds__(256, 1)
void attn_kernel(const float* __restrict__ qf, const float* __restrict__ kf,
                 const float* __restrict__ qkv, float* __restrict__ att_out)
{
    extern __shared__ float sm[];
    float* As    = sm;                       // [2][16][132]
    float* Bs    = sm + 2 * SLAB;            // [2][16][132]
    float* S_s   = Bs + 2 * SLAB;            // [128][128] XOR-swizzled
    float* v_s   = S_s + 128 * 128;          // [128][64]
    float* den_s = v_s + 128 * 64;           // [128]

    const int tid = threadIdx.x;
    const int bh = blockIdx.y;               // 0..95
    const int b = bh / Hh, h = bh % Hh;
    const int n0 = blockIdx.x << 7;

    const int ty = tid >> 4, tx = tid & 15;  // S-compute mapping
    const int rg = tid >> 3;                 // phase-2: rows rg*4..+3
    const int dg = tid & 7;                  // phase-2: d in [dg*8, dg*8+8)
    const int ib = rg * 4;

    const int r  = tid >> 2;                 // tile-load helpers
    const int c4 = tid & 3;
    const int cb = c4 * 4;

    const float* qf_bh = qf + (size_t)bh * Nn * Mm;
    const float* kf_bh = kf + (size_t)bh * Nn * Mm;

    ull out2[16];
#pragma unroll
    for (int i = 0; i < 16; ++i) out2[i] = 0ull;
    float den[4] = {0.f, 0.f, 0.f, 0.f};

#pragma unroll 1
    for (int kt = 0; kt < 8; ++kt) {
        const int j0 = kt << 7;
        __syncthreads();   // protect v_s / S_s from previous phase 2

        // load v tile [128][64] (consumed only in phase 2 -> latency hidden)
#pragma unroll
        for (int p = 0; p < 8; ++p) {
            int f4 = tid + p * 256;
            int j = f4 >> 4, dq = f4 & 15;
            float4 vv = *(const float4*)(qkv + (size_t)(b * Nn + j0 + j) * (3 * Cc)
                                         + 2 * Cc + h * Dd + dq * 4);
            *(float4*)(v_s + j * 64 + dq * 4) = vv;
        }

        // ---- S = qf_tile @ kf_tile^T (f32x2 microkernel, m in 16-chunks) ----
        ull S2[4][8];
#pragma unroll
        for (int i = 0; i < 4; ++i)
#pragma unroll
            for (int j = 0; j < 8; ++j) S2[i][j] = 0ull;

        const float* aRow0 = qf_bh + (size_t)(n0 + r)      * Mm + c4 * 4;
        const float* aRow1 = qf_bh + (size_t)(n0 + 64 + r) * Mm + c4 * 4;
        const float* bRow0 = kf_bh + (size_t)(j0 + r)      * Mm + c4 * 4;
        const float* bRow1 = kf_bh + (size_t)(j0 + 64 + r) * Mm + c4 * 4;

        // prefetch mc = 0
        float4 pa0 = *(const float4*)(aRow0);
        float4 pa1 = *(const float4*)(aRow1);
        float4 pb0 = *(const float4*)(bRow0);
        float4 pb1 = *(const float4*)(bRow1);

#pragma unroll 1
        for (int mc = 0; mc < 8; ++mc) {
            const int p = mc & 1;
            float* Asb = As + p * SLAB;
            float* Bsb = Bs + p * SLAB;
            STORE_SLAB(Asb, pa0, pa1, cb, r);
            STORE_SLAB(Bsb, pb0, pb1, cb, r);
            __syncthreads();                     // one barrier per chunk
            if (mc < 7) {                        // prefetch next m-chunk
                const int mo = (mc + 1) * 16;
                pa0 = *(const float4*)(aRow0 + mo);
                pa1 = *(const float4*)(aRow1 + mo);
                pb0 = *(const float4*)(bRow0 + mo);
                pb1 = *(const float4*)(bRow1 + mo);
            }
            MICRO_FMA(S2, Asb, Bsb, ty, tx);
        }

        // ---- stage S in smem (conflict-free swizzle: phys col = i ^ swiz(j)) ----
#pragma unroll
        for (int ip = 0; ip < 4; ++ip)
#pragma unroll
            for (int jj = 0; jj < 8; ++jj) {
                float2 s = unpack2(S2[ip][jj]);
                int i = ty * 8 + ip * 2;
                int j = tx * 8 + jj;
                int key = swiz(j);
                S_s[j * 128 + ((i)     ^ key)] = s.x;
                S_s[j * 128 + ((i + 1) ^ key)] = s.y;
            }
        __syncthreads();

        // ---- phase 2: out += S @ v, den += |S| @ 1 ----
#pragma unroll 2
        for (int j = 0; j < 128; ++j) {
            const int key = swiz(j);
            const float* Srow = S_s + j * 128;
            float s0 = Srow[(ib + 0) ^ key];
            float s1 = Srow[(ib + 1) ^ key];
            float s2 = Srow[(ib + 2) ^ key];
            float s3 = Srow[(ib + 3) ^ key];
            if (dg == 0) {
                den[0] += fabsf(s0); den[1] += fabsf(s1);
                den[2] += fabsf(s2); den[3] += fabsf(s3);
            }
            ull sd0 = pack2(s0, s0), sd1 = pack2(s1, s1);
            ull sd2 = pack2(s2, s2), sd3 = pack2(s3, s3);
            const ulonglong2* vp = (const ulonglong2*)(v_s + j * 64 + dg * 8);
            ulonglong2 va = vp[0], vb = vp[1];
            fma2(out2[ 0], sd0, va.x); fma2(out2[ 1], sd0, va.y);
            fma2(out2[ 2], sd0, vb.x); fma2(out2[ 3], sd0, vb.y);
            fma2(out2[ 4], sd1, va.x); fma2(out2[ 5], sd1, va.y);
            fma2(out2[ 6], sd1, vb.x); fma2(out2[ 7], sd1, vb.y);
            fma2(out2[ 8], sd2, va.x); fma2(out2[ 9], sd2, va.y);
            fma2(out2[10], sd2, vb.x); fma2(out2[11], sd2, vb.y);
            fma2(out2[12], sd3, va.x); fma2(out2[13], sd3, va.y);
            fma2(out2[14], sd3, vb.x); fma2(out2[15], sd3, vb.y);
        }
    }

    // ---- L1-normalize and write [b][n][h*D + d] ----
    __syncthreads();
    if (dg == 0) {
        den_s[ib + 0] = den[0]; den_s[ib + 1] = den[1];
        den_s[ib + 2] = den[2]; den_s[ib + 3] = den[3];
    }
    __syncthreads();
#pragma unroll
    for (int rr = 0; rr < 4; ++rr) {
        int i = ib + rr;
        float scale = 1.0f / fmaxf(den_s[i], 1e-12f);
        float* op = att_out + (size_t)(b * Nn + n0 + i) * Cc + h * Dd + dg * 8;
        float2 f0 = unpack2(out2[rr * 4 + 0]);
        float2 f1 = unpack2(out2[rr * 4 + 1]);
        float2 f2 = unpack2(out2[rr * 4 + 2]);
        float2 f3 = unpack2(out2[rr * 4 + 3]);
        *(float4*)(op)     = make_float4(f0.x * scale, f0.y * scale, f1.x * scale, f1.y * scale);
        *(float4*)(op + 4) = make_float4(f2.x * scale, f2.y * scale, f3.x * scale, f3.y * scale);
    }
}

// =====================================================================
extern "C" void kernel_launch(void* const* d_in, const int* in_sizes, int n_in,
                              void* d_out, int out_size)
{
    const float* x      = (const float*)d_in[0];
    const float* qkv_w  = (const float*)d_in[1];
    const float* proj_w = (const float*)d_in[2];
    const float* proj_b = (const float*)d_in[3];
    const float* rand_m = (const float*)d_in[4];
    float* out = (float*)d_out;

    float *qkv, *qf, *kf, *att;
    cudaGetSymbolAddress((void**)&qkv, g_qkv);
    cudaGetSymbolAddress((void**)&qf,  g_qf);
    cudaGetSymbolAddress((void**)&kf,  g_kf);
    cudaGetSymbolAddress((void**)&att, g_att);

    // 1) qkv = x @ qkv_w^T          [8192,2304]
    gemm_nt_kernel<<<dim3(3 * Cc / 128, Bb * Nn / 128), 256>>>(
        x, qkv_w, nullptr, qkv, Bb * Nn, 3 * Cc, Cc);

    // 2) feature maps qf, kf        [B,H,N,M]
    feat_kernel<<<dim3(Nn / 16, Hh, 2 * Bb), 128>>>(qkv, rand_m, qf, kf);

    // 3) fused linear attention -> att [B,N,C]
    cudaFuncSetAttribute(attn_kernel, cudaFuncAttributeMaxDynamicSharedMemorySize,
                         ATT_SMEM_BYTES);
    attn_kernel<<<dim3(Nn / 128, Bb * Hh), 256, ATT_SMEM_BYTES>>>(qf, kf, qkv, att);

    // 4) out = att @ proj_w^T + proj_b   [8192,768]
    gemm_nt_kernel<<<dim3(Cc / 128, Bb * Nn / 128), 256>>>(
        att, proj_w, proj_b, out, Bb * Nn, Cc, Cc);
}